// round 15
// baseline (speedup 1.0000x reference)
#include <cuda_runtime.h>
#include <cuda_fp16.h>
#include <math.h>
#include <stdint.h>

// Problem constants (fixed by the dataset)
#define N_ 50000
#define E_ 800000
#define NB_SCAN ((N_ + 1023) / 1024)   // 49

// ---------------------------------------------------------------------------
// Static device scratch. xl fp16 (gathered per edge), xr/h fp32.
// ---------------------------------------------------------------------------
__device__ __align__(16) __half g_xlh[N_ * 128];
__device__ __align__(16) float  g_xr [N_ * 128];
__device__ __align__(16) float  g_h  [N_ * 128];
__device__ int   g_rowptr[N_ + 1];
__device__ int   g_cnt[N_];
__device__ int   g_col[E_];
__device__ int   g_esrc[E_];
__device__ int   g_edst[E_];
__device__ int   g_is64;
__device__ int   g_bsum[64];
__device__ int   g_boff[64];

// ---------------------------------------------------------------------------
// Edge-index dtype sniff + zero counters (fused)
// ---------------------------------------------------------------------------
__global__ void k_detect_zero(const int* __restrict__ ei32) {
    int i = blockIdx.x * blockDim.x + threadIdx.x;
    if (i < N_) g_cnt[i] = 0;
    if (blockIdx.x == 0) {
        __shared__ int nz;
        if (threadIdx.x == 0) nz = 0;
        __syncthreads();
        int local = 0;
        for (int k = threadIdx.x; k < 4096; k += blockDim.x)
            local |= ei32[2 * k + 1];
        if (local) atomicOr(&nz, 1);
        __syncthreads();
        if (threadIdx.x == 0) g_is64 = (nz == 0) ? 1 : 0;
    }
}

__global__ void k_convert_hist(const void* __restrict__ ei) {
    int e = blockIdx.x * blockDim.x + threadIdx.x;
    if (e >= E_) return;
    int s, d;
    if (g_is64) {
        const long long* p = (const long long*)ei;
        s = (int)p[e];
        d = (int)p[E_ + e];
    } else {
        const int* p = (const int*)ei;
        s = p[e];
        d = p[E_ + e];
    }
    s = min(max(s, 0), N_ - 1);
    d = min(max(d, 0), N_ - 1);
    g_esrc[e] = s;
    g_edst[e] = d;
    atomicAdd(&g_cnt[d], 1);
}

// ---------------------------------------------------------------------------
// Multi-block exclusive scan of g_cnt -> g_rowptr (3 phases)
// ---------------------------------------------------------------------------
__global__ void k_scan1() {
    __shared__ int sh[1024];
    int b = blockIdx.x, t = threadIdx.x;
    int idx = b * 1024 + t;
    int v = (idx < N_) ? g_cnt[idx] : 0;
    sh[t] = v;
    __syncthreads();
#pragma unroll
    for (int off = 1; off < 1024; off <<= 1) {
        int x = (t >= off) ? sh[t - off] : 0;
        __syncthreads();
        sh[t] += x;
        __syncthreads();
    }
    if (idx < N_) g_rowptr[idx] = sh[t] - v;
    if (t == 1023) g_bsum[b] = sh[1023];
}

__global__ void k_scan2() {
    __shared__ int sh[64];
    int t = threadIdx.x;
    int v = (t < NB_SCAN) ? g_bsum[t] : 0;
    sh[t] = v;
    __syncthreads();
#pragma unroll
    for (int off = 1; off < 64; off <<= 1) {
        int x = (t >= off) ? sh[t - off] : 0;
        __syncthreads();
        sh[t] += x;
        __syncthreads();
    }
    if (t < NB_SCAN) g_boff[t] = sh[t] - v;
    if (t == 63) g_rowptr[N_] = sh[63];
}

__global__ void k_scan3() {
    int i = blockIdx.x * blockDim.x + threadIdx.x;
    if (i < N_) {
        g_rowptr[i] += g_boff[i >> 10];
        g_cnt[i] = 0;
    }
}

__global__ void k_scatter() {
    int e = blockIdx.x * blockDim.x + threadIdx.x;
    if (e < E_) {
        int d = g_edst[e];
        int p = atomicAdd(&g_cnt[d], 1);
        int pos = g_rowptr[d] + p;
        if (pos >= 0 && pos < E_) g_col[pos] = g_esrc[e];
    }
}

// ---------------------------------------------------------------------------
// fp16 tensor-core fused dual GEMM (m16n8k16.f16, fp32 accum):
//   xl (fp16) = A @ Wl, xr (fp32) = A @ Wr   (A: [N,128], W: [128,HALF])
// Block tile 128x64, 8 warps (4Mx2N), warp tile 32x32, K chunks of 32,
// double-buffered packed-half2 smem. fp16 mantissa == tf32 mantissa (10 bits),
// so numerics match the previous tf32 version while halving HMMA count.
// ---------------------------------------------------------------------------
__device__ __forceinline__ void mma_f16(float c[4], const uint32_t a[4], const uint32_t b[2]) {
    asm volatile(
        "mma.sync.aligned.m16n8k16.row.col.f32.f16.f16.f32 "
        "{%0,%1,%2,%3}, {%4,%5,%6,%7}, {%8,%9}, {%0,%1,%2,%3};"
        : "+f"(c[0]), "+f"(c[1]), "+f"(c[2]), "+f"(c[3])
        : "r"(a[0]), "r"(a[1]), "r"(a[2]), "r"(a[3]), "r"(b[0]), "r"(b[1]));
}

__device__ __forceinline__ uint32_t pack_h2(float x, float y) {
    __half2 h = __floats2half2_rn(x, y);
    return *reinterpret_cast<uint32_t*>(&h);
}

template <int HALF, int AFROMH>
__global__ void __launch_bounds__(256) k_gemm_fp16(const float* __restrict__ A_ext,
                                                   const float* __restrict__ Wl,
                                                   const float* __restrict__ Wr) {
    // packed half2 tiles: column j holds k = 2j, 2j+1. Row stride 20 (pad 4)
    // -> fragment LDS banks (20*g + tig) % 32 all-distinct: conflict-free.
    __shared__ uint32_t As16[2][128][20];   // [row][j], j in [0,16)
    __shared__ uint32_t Bs16[2][64][20];    // [n]  [j], j in [0,16)

    const float* A = AFROMH ? (const float*)g_h : A_ext;

    const int HT = HALF / 64;
    int row0 = blockIdx.x * 128;
    int by = blockIdx.y;
    bool isXL = (by < HT);
    const float* W = isXL ? Wl : Wr;
    int colbase = (by % HT) * 64;

    int tid  = threadIdx.x;
    int lane = tid & 31;
    int wid  = tid >> 5;
    int warpM = wid & 3;
    int warpN = wid >> 2;
    int g   = lane >> 2;
    int tig = lane & 3;
    int mrow = warpM * 32;
    int ncol = warpN * 32;

    // staging coords: A: 1024 float4 (128 rows x 8), B: 1024 uint32 (16j x 64n)
    int ra_r[4], ra_kq[4], rb_j[4], rb_n[4];
#pragma unroll
    for (int l = 0; l < 4; l++) {
        int idx = tid + l * 256;
        ra_r[l]  = idx >> 3;
        ra_kq[l] = idx & 7;
        rb_j[l]  = idx >> 6;
        rb_n[l]  = idx & 63;
    }

    float c[2][4][4];
#pragma unroll
    for (int mt = 0; mt < 2; mt++)
#pragma unroll
        for (int nt = 0; nt < 4; nt++)
#pragma unroll
            for (int i = 0; i < 4; i++) c[mt][nt][i] = 0.f;

    // Prologue: chunk 0 -> buffer 0
    {
#pragma unroll
        for (int l = 0; l < 4; l++) {
            int grow = row0 + ra_r[l];
            float4 v = make_float4(0.f, 0.f, 0.f, 0.f);
            if (grow < N_) v = *(const float4*)&A[grow * 128 + ra_kq[l] * 4];
            As16[0][ra_r[l]][ra_kq[l] * 2    ] = pack_h2(v.x, v.y);
            As16[0][ra_r[l]][ra_kq[l] * 2 + 1] = pack_h2(v.z, v.w);
        }
#pragma unroll
        for (int l = 0; l < 4; l++) {
            float w0 = W[(2 * rb_j[l]    ) * HALF + colbase + rb_n[l]];
            float w1 = W[(2 * rb_j[l] + 1) * HALF + colbase + rb_n[l]];
            Bs16[0][rb_n[l]][rb_j[l]] = pack_h2(w0, w1);
        }
    }
    __syncthreads();

    for (int kc = 0; kc < 4; kc++) {
        int cur = kc & 1;
        // prefetch next chunk into registers
        float4 pa[4];
        float pb0[4], pb1[4];
        if (kc < 3) {
            int kn = kc + 1;
#pragma unroll
            for (int l = 0; l < 4; l++) {
                int grow = row0 + ra_r[l];
                pa[l] = make_float4(0.f, 0.f, 0.f, 0.f);
                if (grow < N_) pa[l] = *(const float4*)&A[grow * 128 + kn * 32 + ra_kq[l] * 4];
            }
#pragma unroll
            for (int l = 0; l < 4; l++) {
                pb0[l] = W[(kn * 32 + 2 * rb_j[l]    ) * HALF + colbase + rb_n[l]];
                pb1[l] = W[(kn * 32 + 2 * rb_j[l] + 1) * HALF + colbase + rb_n[l]];
            }
        }

#pragma unroll
        for (int ks = 0; ks < 2; ks++) {
            int j0 = ks * 8;
            uint32_t a[2][4], b[4][2];
#pragma unroll
            for (int mt = 0; mt < 2; mt++) {
                int r = mrow + mt * 16 + g;
                a[mt][0] = As16[cur][r    ][j0 + tig];
                a[mt][1] = As16[cur][r + 8][j0 + tig];
                a[mt][2] = As16[cur][r    ][j0 + tig + 4];
                a[mt][3] = As16[cur][r + 8][j0 + tig + 4];
            }
#pragma unroll
            for (int nt = 0; nt < 4; nt++) {
                int n = ncol + nt * 8 + g;
                b[nt][0] = Bs16[cur][n][j0 + tig];
                b[nt][1] = Bs16[cur][n][j0 + tig + 4];
            }
#pragma unroll
            for (int mt = 0; mt < 2; mt++)
#pragma unroll
                for (int nt = 0; nt < 4; nt++)
                    mma_f16(c[mt][nt], a[mt], b[nt]);
        }

        if (kc < 3) {
            int nxt = cur ^ 1;
#pragma unroll
            for (int l = 0; l < 4; l++) {
                As16[nxt][ra_r[l]][ra_kq[l] * 2    ] = pack_h2(pa[l].x, pa[l].y);
                As16[nxt][ra_r[l]][ra_kq[l] * 2 + 1] = pack_h2(pa[l].z, pa[l].w);
            }
#pragma unroll
            for (int l = 0; l < 4; l++)
                Bs16[nxt][rb_n[l]][rb_j[l]] = pack_h2(pb0[l], pb1[l]);
        }
        __syncthreads();
    }

    // Epilogue: xl -> fp16, xr -> fp32
#pragma unroll
    for (int mt = 0; mt < 2; mt++) {
        int r0 = row0 + mrow + mt * 16 + g;
#pragma unroll
        for (int nt = 0; nt < 4; nt++) {
            int cb = colbase + ncol + nt * 8 + tig * 2;
            if (isXL) {
                if (r0 < N_)
                    *(__half2*)&g_xlh[r0 * HALF + cb] =
                        __floats2half2_rn(c[mt][nt][0], c[mt][nt][1]);
                if (r0 + 8 < N_)
                    *(__half2*)&g_xlh[(r0 + 8) * HALF + cb] =
                        __floats2half2_rn(c[mt][nt][2], c[mt][nt][3]);
            } else {
                if (r0 < N_)
                    *(float2*)&g_xr[r0 * HALF + cb] = make_float2(c[mt][nt][0], c[mt][nt][1]);
                if (r0 + 8 < N_)
                    *(float2*)&g_xr[(r0 + 8) * HALF + cb] = make_float2(c[mt][nt][2], c[mt][nt][3]);
            }
        }
    }
}

// ---------------------------------------------------------------------------
// fp16 gather helpers
// ---------------------------------------------------------------------------
__device__ __forceinline__ float4 ldxl128(int node, int off) {
    uint2 u = *(const uint2*)&g_xlh[node * 128 + off];
    __half2 h0 = *reinterpret_cast<__half2*>(&u.x);
    __half2 h1 = *reinterpret_cast<__half2*>(&u.y);
    float2 a = __half22float2(h0);
    float2 b = __half22float2(h1);
    return make_float4(a.x, a.y, b.x, b.y);
}

__device__ __forceinline__ float2 ldxl64(int node, int off) {
    __half2 h = *(const __half2*)&g_xlh[node * 64 + off];
    return __half22float2(h);
}

// ---------------------------------------------------------------------------
// Edge aggregation: one warp per dst node, online segment softmax, 4-edge
// unrolled, fused bias + ELU (layers 1/2, 128 channels)
// ---------------------------------------------------------------------------
__device__ __forceinline__ float leaky(float x) { return x > 0.f ? x : 0.2f * x; }

__device__ __forceinline__ float edot(const float4 v, const float4 xr, const float4 a) {
    float q = leaky(v.x + xr.x) * a.x + leaky(v.y + xr.y) * a.y
            + leaky(v.z + xr.z) * a.z + leaky(v.w + xr.w) * a.w;
    q += __shfl_xor_sync(0xffffffffu, q, 1);
    q += __shfl_xor_sync(0xffffffffu, q, 2);
    q += __shfl_xor_sync(0xffffffffu, q, 4);
    return q;
}

__global__ void k_agg128(const float* __restrict__ att,
                         const float* __restrict__ bias) {
    int gw = (blockIdx.x * blockDim.x + threadIdx.x) >> 5;
    int lane = threadIdx.x & 31;
    if (gw >= N_) return;
    int off = lane * 4;
    float4 xr4 = *(const float4*)&g_xr[gw * 128 + off];
    float4 a4  = *(const float4*)&att[off];
    float4 xls = ldxl128(gw, off);

    float m = edot(xls, xr4, a4), s = 1.f;
    float4 acc = xls;

    int beg = g_rowptr[gw], end = g_rowptr[gw + 1];
    int j = beg;
    for (; j + 3 < end; j += 4) {
        int s0 = g_col[j], s1 = g_col[j + 1], s2 = g_col[j + 2], s3 = g_col[j + 3];
        float4 v0 = ldxl128(s0, off);
        float4 v1 = ldxl128(s1, off);
        float4 v2 = ldxl128(s2, off);
        float4 v3 = ldxl128(s3, off);
        float q0 = edot(v0, xr4, a4);
        float q1 = edot(v1, xr4, a4);
        float q2 = edot(v2, xr4, a4);
        float q3 = edot(v3, xr4, a4);
        float nm = fmaxf(fmaxf(m, fmaxf(q0, q1)), fmaxf(q2, q3));
        float co = __expf(m - nm);
        float w0 = __expf(q0 - nm);
        float w1 = __expf(q1 - nm);
        float w2 = __expf(q2 - nm);
        float w3 = __expf(q3 - nm);
        s = s * co + w0 + w1 + w2 + w3;
        acc.x = acc.x * co + w0 * v0.x + w1 * v1.x + w2 * v2.x + w3 * v3.x;
        acc.y = acc.y * co + w0 * v0.y + w1 * v1.y + w2 * v2.y + w3 * v3.y;
        acc.z = acc.z * co + w0 * v0.z + w1 * v1.z + w2 * v2.z + w3 * v3.z;
        acc.w = acc.w * co + w0 * v0.w + w1 * v1.w + w2 * v2.w + w3 * v3.w;
        m = nm;
    }
    for (; j < end; j++) {
        int src = g_col[j];
        float4 v = ldxl128(src, off);
        float q = edot(v, xr4, a4);
        float nm = fmaxf(m, q);
        float co = __expf(m - nm);
        float w  = __expf(q - nm);
        s = s * co + w;
        acc.x = acc.x * co + w * v.x;
        acc.y = acc.y * co + w * v.y;
        acc.z = acc.z * co + w * v.z;
        acc.w = acc.w * co + w * v.w;
        m = nm;
    }
    float inv = 1.f / s;
    float4 b4 = *(const float4*)&bias[off];
    float4 o;
    o.x = acc.x * inv + b4.x;
    o.y = acc.y * inv + b4.y;
    o.z = acc.z * inv + b4.z;
    o.w = acc.w * inv + b4.w;
    o.x = o.x > 0.f ? o.x : expm1f(o.x);
    o.y = o.y > 0.f ? o.y : expm1f(o.y);
    o.z = o.z > 0.f ? o.z : expm1f(o.z);
    o.w = o.w > 0.f ? o.w : expm1f(o.w);
    *(float4*)&g_h[gw * 128 + off] = o;
}

// ---------------------------------------------------------------------------
// Layer-3 aggregation (64 channels; lane owns 2), fused bias + log_softmax
// ---------------------------------------------------------------------------
__device__ __forceinline__ float edot2(const float2 v, const float2 xr, const float2 a) {
    float q = leaky(v.x + xr.x) * a.x + leaky(v.y + xr.y) * a.y;
    q += __shfl_xor_sync(0xffffffffu, q, 1);
    q += __shfl_xor_sync(0xffffffffu, q, 2);
    q += __shfl_xor_sync(0xffffffffu, q, 4);
    return q;
}

__global__ void k_agg64(const float* __restrict__ att,
                        const float* __restrict__ bias,
                        float* __restrict__ outp) {
    int gw = (blockIdx.x * blockDim.x + threadIdx.x) >> 5;
    int lane = threadIdx.x & 31;
    if (gw >= N_) return;
    int off = lane * 2;
    float2 xr2 = *(const float2*)&g_xr[gw * 64 + off];
    float2 a2  = *(const float2*)&att[off];
    float2 xls = ldxl64(gw, off);

    float m = edot2(xls, xr2, a2), s = 1.f;
    float2 acc = xls;

    int beg = g_rowptr[gw], end = g_rowptr[gw + 1];
    int j = beg;
    for (; j + 3 < end; j += 4) {
        int s0 = g_col[j], s1 = g_col[j + 1], s2 = g_col[j + 2], s3 = g_col[j + 3];
        float2 v0 = ldxl64(s0, off);
        float2 v1 = ldxl64(s1, off);
        float2 v2 = ldxl64(s2, off);
        float2 v3 = ldxl64(s3, off);
        float q0 = edot2(v0, xr2, a2);
        float q1 = edot2(v1, xr2, a2);
        float q2 = edot2(v2, xr2, a2);
        float q3 = edot2(v3, xr2, a2);
        float nm = fmaxf(fmaxf(m, fmaxf(q0, q1)), fmaxf(q2, q3));
        float co = __expf(m - nm);
        float w0 = __expf(q0 - nm);
        float w1 = __expf(q1 - nm);
        float w2 = __expf(q2 - nm);
        float w3 = __expf(q3 - nm);
        s = s * co + w0 + w1 + w2 + w3;
        acc.x = acc.x * co + w0 * v0.x + w1 * v1.x + w2 * v2.x + w3 * v3.x;
        acc.y = acc.y * co + w0 * v0.y + w1 * v1.y + w2 * v2.y + w3 * v3.y;
        m = nm;
    }
    for (; j < end; j++) {
        int src = g_col[j];
        float2 v = ldxl64(src, off);
        float q = edot2(v, xr2, a2);
        float nm = fmaxf(m, q);
        float co = __expf(m - nm);
        float w  = __expf(q - nm);
        s = s * co + w;
        acc.x = acc.x * co + w * v.x;
        acc.y = acc.y * co + w * v.y;
        m = nm;
    }
    float inv = 1.f / s;
    float o0 = acc.x * inv + bias[off];
    float o1 = acc.y * inv + bias[off + 1];

    float mx = fmaxf(o0, o1);
#pragma unroll
    for (int d = 16; d >= 1; d >>= 1)
        mx = fmaxf(mx, __shfl_xor_sync(0xffffffffu, mx, d));
    float se = __expf(o0 - mx) + __expf(o1 - mx);
#pragma unroll
    for (int d = 16; d >= 1; d >>= 1)
        se += __shfl_xor_sync(0xffffffffu, se, d);
    float lse = logf(se);
    outp[gw * 64 + off]     = o0 - mx - lse;
    outp[gw * 64 + off + 1] = o1 - mx - lse;
}

// ---------------------------------------------------------------------------
// Host launch — R6 schedule: CSR on side stream hidden under gemm1,
// then serial layer chain.
// ---------------------------------------------------------------------------
extern "C" void kernel_launch(void* const* d_in, const int* in_sizes, int n_in,
                              void* d_out, int out_size) {
    const float* x    = (const float*)d_in[0];
    const void*  ei   = d_in[1];
    const float* Wl1  = (const float*)d_in[2];
    const float* Wr1  = (const float*)d_in[3];
    const float* att1 = (const float*)d_in[4];
    const float* b1   = (const float*)d_in[5];
    const float* Wl2  = (const float*)d_in[6];
    const float* Wr2  = (const float*)d_in[7];
    const float* att2 = (const float*)d_in[8];
    const float* b2   = (const float*)d_in[9];
    const float* Wl3  = (const float*)d_in[10];
    const float* Wr3  = (const float*)d_in[11];
    const float* att3 = (const float*)d_in[12];
    const float* b3   = (const float*)d_in[13];
    float* out = (float*)d_out;

    static cudaStream_t s2 = nullptr;
    static cudaEvent_t evFork = nullptr, evJoin = nullptr;
    if (s2 == nullptr) {
        cudaStreamCreateWithFlags(&s2, cudaStreamNonBlocking);
        cudaEventCreateWithFlags(&evFork, cudaEventDisableTiming);
        cudaEventCreateWithFlags(&evJoin, cudaEventDisableTiming);
    }

    dim3 g12((N_ + 127) / 128, 4);
    dim3 g3 ((N_ + 127) / 128, 2);
    int aggBlocks = (N_ * 32 + 255) / 256;

    // Fork: CSR build on s2, concurrent with layer-1 GEMM on main stream
    cudaEventRecord(evFork, 0);
    cudaStreamWaitEvent(s2, evFork, 0);

    k_detect_zero<<<(N_ + 255) / 256, 256, 0, s2>>>((const int*)ei);
    k_convert_hist<<<(E_ + 255) / 256, 256, 0, s2>>>(ei);
    k_scan1<<<NB_SCAN, 1024, 0, s2>>>();
    k_scan2<<<1, 64, 0, s2>>>();
    k_scan3<<<(N_ + 255) / 256, 256, 0, s2>>>();
    k_scatter<<<(E_ + 255) / 256, 256, 0, s2>>>();
    cudaEventRecord(evJoin, s2);

    // Layer-1 GEMM on main stream (independent of CSR)
    k_gemm_fp16<128, 0><<<g12, 256>>>(x, Wl1, Wr1);
    cudaStreamWaitEvent(0, evJoin, 0);

    k_agg128<<<aggBlocks, 256>>>(att1, b1);
    // Layer 2
    k_gemm_fp16<128, 1><<<g12, 256>>>(nullptr, Wl2, Wr2);
    k_agg128<<<aggBlocks, 256>>>(att2, b2);
    // Layer 3 + log_softmax
    k_gemm_fp16<64, 1><<<g3, 256>>>(nullptr, Wl3, Wr3);
    k_agg64<<<aggBlocks, 256>>>(att3, b3, out);
}

// round 16
// speedup vs baseline: 1.0076x; 1.0076x over previous
#include <cuda_runtime.h>
#include <cuda_fp16.h>
#include <math.h>
#include <stdint.h>

// Problem constants (fixed by the dataset)
#define N_ 50000
#define E_ 800000
#define NB_SCAN ((N_ + 1023) / 1024)   // 49

// ---------------------------------------------------------------------------
// Static device scratch. xl fp16 (gathered per edge), xr/h fp32.
// ---------------------------------------------------------------------------
__device__ __align__(16) __half g_xlh[N_ * 128];
__device__ __align__(16) float  g_xr [N_ * 128];
__device__ __align__(16) float  g_h  [N_ * 128];
__device__ int   g_rowptr[N_ + 1];
__device__ int   g_cnt[N_];
__device__ int   g_col[E_];
__device__ int   g_esrc[E_];
__device__ int   g_edst[E_];
__device__ int   g_is64;
__device__ int   g_bsum[64];
__device__ int   g_boff[64];

// ---------------------------------------------------------------------------
// Edge-index dtype sniff + zero counters (fused)
// ---------------------------------------------------------------------------
__global__ void k_detect_zero(const int* __restrict__ ei32) {
    int i = blockIdx.x * blockDim.x + threadIdx.x;
    if (i < N_) g_cnt[i] = 0;
    if (blockIdx.x == 0) {
        __shared__ int nz;
        if (threadIdx.x == 0) nz = 0;
        __syncthreads();
        int local = 0;
        for (int k = threadIdx.x; k < 4096; k += blockDim.x)
            local |= ei32[2 * k + 1];
        if (local) atomicOr(&nz, 1);
        __syncthreads();
        if (threadIdx.x == 0) g_is64 = (nz == 0) ? 1 : 0;
    }
}

__global__ void k_convert_hist(const void* __restrict__ ei) {
    int e = blockIdx.x * blockDim.x + threadIdx.x;
    if (e >= E_) return;
    int s, d;
    if (g_is64) {
        const long long* p = (const long long*)ei;
        s = (int)p[e];
        d = (int)p[E_ + e];
    } else {
        const int* p = (const int*)ei;
        s = p[e];
        d = p[E_ + e];
    }
    s = min(max(s, 0), N_ - 1);
    d = min(max(d, 0), N_ - 1);
    g_esrc[e] = s;
    g_edst[e] = d;
    atomicAdd(&g_cnt[d], 1);
}

// ---------------------------------------------------------------------------
// Multi-block exclusive scan of g_cnt -> g_rowptr (3 phases)
// ---------------------------------------------------------------------------
__global__ void k_scan1() {
    __shared__ int sh[1024];
    int b = blockIdx.x, t = threadIdx.x;
    int idx = b * 1024 + t;
    int v = (idx < N_) ? g_cnt[idx] : 0;
    sh[t] = v;
    __syncthreads();
#pragma unroll
    for (int off = 1; off < 1024; off <<= 1) {
        int x = (t >= off) ? sh[t - off] : 0;
        __syncthreads();
        sh[t] += x;
        __syncthreads();
    }
    if (idx < N_) g_rowptr[idx] = sh[t] - v;
    if (t == 1023) g_bsum[b] = sh[1023];
}

__global__ void k_scan2() {
    __shared__ int sh[64];
    int t = threadIdx.x;
    int v = (t < NB_SCAN) ? g_bsum[t] : 0;
    sh[t] = v;
    __syncthreads();
#pragma unroll
    for (int off = 1; off < 64; off <<= 1) {
        int x = (t >= off) ? sh[t - off] : 0;
        __syncthreads();
        sh[t] += x;
        __syncthreads();
    }
    if (t < NB_SCAN) g_boff[t] = sh[t] - v;
    if (t == 63) g_rowptr[N_] = sh[63];
}

__global__ void k_scan3() {
    int i = blockIdx.x * blockDim.x + threadIdx.x;
    if (i < N_) {
        g_rowptr[i] += g_boff[i >> 10];
        g_cnt[i] = 0;
    }
}

__global__ void k_scatter() {
    int e = blockIdx.x * blockDim.x + threadIdx.x;
    if (e < E_) {
        int d = g_edst[e];
        int p = atomicAdd(&g_cnt[d], 1);
        int pos = g_rowptr[d] + p;
        if (pos >= 0 && pos < E_) g_col[pos] = g_esrc[e];
    }
}

// ---------------------------------------------------------------------------
// fp16 tensor-core fused dual GEMM (m16n8k16.f16, fp32 accum):
//   xl (fp16) = A @ Wl, xr (fp32) = A @ Wr   (A: [N,128], W: [128,HALF])
// Block tile 128x64, 8 warps (4Mx2N), warp tile 32x32, K chunks of 32,
// double-buffered packed-half2 smem. fp16 mantissa == tf32 mantissa (10 bits),
// so numerics match the previous tf32 version while halving HMMA count.
// ---------------------------------------------------------------------------
__device__ __forceinline__ void mma_f16(float c[4], const uint32_t a[4], const uint32_t b[2]) {
    asm volatile(
        "mma.sync.aligned.m16n8k16.row.col.f32.f16.f16.f32 "
        "{%0,%1,%2,%3}, {%4,%5,%6,%7}, {%8,%9}, {%0,%1,%2,%3};"
        : "+f"(c[0]), "+f"(c[1]), "+f"(c[2]), "+f"(c[3])
        : "r"(a[0]), "r"(a[1]), "r"(a[2]), "r"(a[3]), "r"(b[0]), "r"(b[1]));
}

__device__ __forceinline__ uint32_t pack_h2(float x, float y) {
    __half2 h = __floats2half2_rn(x, y);
    return *reinterpret_cast<uint32_t*>(&h);
}

template <int HALF, int AFROMH>
__global__ void __launch_bounds__(256) k_gemm_fp16(const float* __restrict__ A_ext,
                                                   const float* __restrict__ Wl,
                                                   const float* __restrict__ Wr) {
    // packed half2 tiles: column j holds k = 2j, 2j+1. Row stride 20 (pad 4)
    // -> fragment LDS banks (20*g + tig) % 32 all-distinct: conflict-free.
    __shared__ uint32_t As16[2][128][20];   // [row][j], j in [0,16)
    __shared__ uint32_t Bs16[2][64][20];    // [n]  [j], j in [0,16)

    const float* A = AFROMH ? (const float*)g_h : A_ext;

    const int HT = HALF / 64;
    int row0 = blockIdx.x * 128;
    int by = blockIdx.y;
    bool isXL = (by < HT);
    const float* W = isXL ? Wl : Wr;
    int colbase = (by % HT) * 64;

    int tid  = threadIdx.x;
    int lane = tid & 31;
    int wid  = tid >> 5;
    int warpM = wid & 3;
    int warpN = wid >> 2;
    int g   = lane >> 2;
    int tig = lane & 3;
    int mrow = warpM * 32;
    int ncol = warpN * 32;

    // staging coords: A: 1024 float4 (128 rows x 8), B: 1024 uint32 (16j x 64n)
    int ra_r[4], ra_kq[4], rb_j[4], rb_n[4];
#pragma unroll
    for (int l = 0; l < 4; l++) {
        int idx = tid + l * 256;
        ra_r[l]  = idx >> 3;
        ra_kq[l] = idx & 7;
        rb_j[l]  = idx >> 6;
        rb_n[l]  = idx & 63;
    }

    float c[2][4][4];
#pragma unroll
    for (int mt = 0; mt < 2; mt++)
#pragma unroll
        for (int nt = 0; nt < 4; nt++)
#pragma unroll
            for (int i = 0; i < 4; i++) c[mt][nt][i] = 0.f;

    // Prologue: chunk 0 -> buffer 0
    {
#pragma unroll
        for (int l = 0; l < 4; l++) {
            int grow = row0 + ra_r[l];
            float4 v = make_float4(0.f, 0.f, 0.f, 0.f);
            if (grow < N_) v = *(const float4*)&A[grow * 128 + ra_kq[l] * 4];
            As16[0][ra_r[l]][ra_kq[l] * 2    ] = pack_h2(v.x, v.y);
            As16[0][ra_r[l]][ra_kq[l] * 2 + 1] = pack_h2(v.z, v.w);
        }
#pragma unroll
        for (int l = 0; l < 4; l++) {
            float w0 = W[(2 * rb_j[l]    ) * HALF + colbase + rb_n[l]];
            float w1 = W[(2 * rb_j[l] + 1) * HALF + colbase + rb_n[l]];
            Bs16[0][rb_n[l]][rb_j[l]] = pack_h2(w0, w1);
        }
    }
    __syncthreads();

    for (int kc = 0; kc < 4; kc++) {
        int cur = kc & 1;
        // prefetch next chunk into registers
        float4 pa[4];
        float pb0[4], pb1[4];
        if (kc < 3) {
            int kn = kc + 1;
#pragma unroll
            for (int l = 0; l < 4; l++) {
                int grow = row0 + ra_r[l];
                pa[l] = make_float4(0.f, 0.f, 0.f, 0.f);
                if (grow < N_) pa[l] = *(const float4*)&A[grow * 128 + kn * 32 + ra_kq[l] * 4];
            }
#pragma unroll
            for (int l = 0; l < 4; l++) {
                pb0[l] = W[(kn * 32 + 2 * rb_j[l]    ) * HALF + colbase + rb_n[l]];
                pb1[l] = W[(kn * 32 + 2 * rb_j[l] + 1) * HALF + colbase + rb_n[l]];
            }
        }

#pragma unroll
        for (int ks = 0; ks < 2; ks++) {
            int j0 = ks * 8;
            uint32_t a[2][4], b[4][2];
#pragma unroll
            for (int mt = 0; mt < 2; mt++) {
                int r = mrow + mt * 16 + g;
                a[mt][0] = As16[cur][r    ][j0 + tig];
                a[mt][1] = As16[cur][r + 8][j0 + tig];
                a[mt][2] = As16[cur][r    ][j0 + tig + 4];
                a[mt][3] = As16[cur][r + 8][j0 + tig + 4];
            }
#pragma unroll
            for (int nt = 0; nt < 4; nt++) {
                int n = ncol + nt * 8 + g;
                b[nt][0] = Bs16[cur][n][j0 + tig];
                b[nt][1] = Bs16[cur][n][j0 + tig + 4];
            }
#pragma unroll
            for (int mt = 0; mt < 2; mt++)
#pragma unroll
                for (int nt = 0; nt < 4; nt++)
                    mma_f16(c[mt][nt], a[mt], b[nt]);
        }

        if (kc < 3) {
            int nxt = cur ^ 1;
#pragma unroll
            for (int l = 0; l < 4; l++) {
                As16[nxt][ra_r[l]][ra_kq[l] * 2    ] = pack_h2(pa[l].x, pa[l].y);
                As16[nxt][ra_r[l]][ra_kq[l] * 2 + 1] = pack_h2(pa[l].z, pa[l].w);
            }
#pragma unroll
            for (int l = 0; l < 4; l++)
                Bs16[nxt][rb_n[l]][rb_j[l]] = pack_h2(pb0[l], pb1[l]);
        }
        __syncthreads();
    }

    // Epilogue: xl -> fp16, xr -> fp32
#pragma unroll
    for (int mt = 0; mt < 2; mt++) {
        int r0 = row0 + mrow + mt * 16 + g;
#pragma unroll
        for (int nt = 0; nt < 4; nt++) {
            int cb = colbase + ncol + nt * 8 + tig * 2;
            if (isXL) {
                if (r0 < N_)
                    *(__half2*)&g_xlh[r0 * HALF + cb] =
                        __floats2half2_rn(c[mt][nt][0], c[mt][nt][1]);
                if (r0 + 8 < N_)
                    *(__half2*)&g_xlh[(r0 + 8) * HALF + cb] =
                        __floats2half2_rn(c[mt][nt][2], c[mt][nt][3]);
            } else {
                if (r0 < N_)
                    *(float2*)&g_xr[r0 * HALF + cb] = make_float2(c[mt][nt][0], c[mt][nt][1]);
                if (r0 + 8 < N_)
                    *(float2*)&g_xr[(r0 + 8) * HALF + cb] = make_float2(c[mt][nt][2], c[mt][nt][3]);
            }
        }
    }
}

// ---------------------------------------------------------------------------
// fp16 gather helpers
// ---------------------------------------------------------------------------
__device__ __forceinline__ float4 ldxl128(int node, int off) {
    uint2 u = *(const uint2*)&g_xlh[node * 128 + off];
    __half2 h0 = *reinterpret_cast<__half2*>(&u.x);
    __half2 h1 = *reinterpret_cast<__half2*>(&u.y);
    float2 a = __half22float2(h0);
    float2 b = __half22float2(h1);
    return make_float4(a.x, a.y, b.x, b.y);
}

__device__ __forceinline__ float2 ldxl64(int node, int off) {
    __half2 h = *(const __half2*)&g_xlh[node * 64 + off];
    return __half22float2(h);
}

// ---------------------------------------------------------------------------
// Edge aggregation: one warp per dst node, online segment softmax, 4-edge
// unrolled, fused bias + ELU (layers 1/2, 128 channels)
// ---------------------------------------------------------------------------
__device__ __forceinline__ float leaky(float x) { return x > 0.f ? x : 0.2f * x; }

__device__ __forceinline__ float edot(const float4 v, const float4 xr, const float4 a) {
    float q = leaky(v.x + xr.x) * a.x + leaky(v.y + xr.y) * a.y
            + leaky(v.z + xr.z) * a.z + leaky(v.w + xr.w) * a.w;
    q += __shfl_xor_sync(0xffffffffu, q, 1);
    q += __shfl_xor_sync(0xffffffffu, q, 2);
    q += __shfl_xor_sync(0xffffffffu, q, 4);
    return q;
}

__global__ void k_agg128(const float* __restrict__ att,
                         const float* __restrict__ bias) {
    int gw = (blockIdx.x * blockDim.x + threadIdx.x) >> 5;
    int lane = threadIdx.x & 31;
    if (gw >= N_) return;
    int off = lane * 4;
    float4 xr4 = *(const float4*)&g_xr[gw * 128 + off];
    float4 a4  = *(const float4*)&att[off];
    float4 xls = ldxl128(gw, off);

    float m = edot(xls, xr4, a4), s = 1.f;
    float4 acc = xls;

    int beg = g_rowptr[gw], end = g_rowptr[gw + 1];
    int j = beg;
    for (; j + 3 < end; j += 4) {
        int s0 = g_col[j], s1 = g_col[j + 1], s2 = g_col[j + 2], s3 = g_col[j + 3];
        float4 v0 = ldxl128(s0, off);
        float4 v1 = ldxl128(s1, off);
        float4 v2 = ldxl128(s2, off);
        float4 v3 = ldxl128(s3, off);
        float q0 = edot(v0, xr4, a4);
        float q1 = edot(v1, xr4, a4);
        float q2 = edot(v2, xr4, a4);
        float q3 = edot(v3, xr4, a4);
        float nm = fmaxf(fmaxf(m, fmaxf(q0, q1)), fmaxf(q2, q3));
        float co = __expf(m - nm);
        float w0 = __expf(q0 - nm);
        float w1 = __expf(q1 - nm);
        float w2 = __expf(q2 - nm);
        float w3 = __expf(q3 - nm);
        s = s * co + w0 + w1 + w2 + w3;
        acc.x = acc.x * co + w0 * v0.x + w1 * v1.x + w2 * v2.x + w3 * v3.x;
        acc.y = acc.y * co + w0 * v0.y + w1 * v1.y + w2 * v2.y + w3 * v3.y;
        acc.z = acc.z * co + w0 * v0.z + w1 * v1.z + w2 * v2.z + w3 * v3.z;
        acc.w = acc.w * co + w0 * v0.w + w1 * v1.w + w2 * v2.w + w3 * v3.w;
        m = nm;
    }
    for (; j < end; j++) {
        int src = g_col[j];
        float4 v = ldxl128(src, off);
        float q = edot(v, xr4, a4);
        float nm = fmaxf(m, q);
        float co = __expf(m - nm);
        float w  = __expf(q - nm);
        s = s * co + w;
        acc.x = acc.x * co + w * v.x;
        acc.y = acc.y * co + w * v.y;
        acc.z = acc.z * co + w * v.z;
        acc.w = acc.w * co + w * v.w;
        m = nm;
    }
    float inv = 1.f / s;
    float4 b4 = *(const float4*)&bias[off];
    float4 o;
    o.x = acc.x * inv + b4.x;
    o.y = acc.y * inv + b4.y;
    o.z = acc.z * inv + b4.z;
    o.w = acc.w * inv + b4.w;
    o.x = o.x > 0.f ? o.x : expm1f(o.x);
    o.y = o.y > 0.f ? o.y : expm1f(o.y);
    o.z = o.z > 0.f ? o.z : expm1f(o.z);
    o.w = o.w > 0.f ? o.w : expm1f(o.w);
    *(float4*)&g_h[gw * 128 + off] = o;
}

// ---------------------------------------------------------------------------
// Layer-3 aggregation (64 channels; lane owns 2), fused bias + log_softmax
// ---------------------------------------------------------------------------
__device__ __forceinline__ float edot2(const float2 v, const float2 xr, const float2 a) {
    float q = leaky(v.x + xr.x) * a.x + leaky(v.y + xr.y) * a.y;
    q += __shfl_xor_sync(0xffffffffu, q, 1);
    q += __shfl_xor_sync(0xffffffffu, q, 2);
    q += __shfl_xor_sync(0xffffffffu, q, 4);
    return q;
}

__global__ void k_agg64(const float* __restrict__ att,
                        const float* __restrict__ bias,
                        float* __restrict__ outp) {
    int gw = (blockIdx.x * blockDim.x + threadIdx.x) >> 5;
    int lane = threadIdx.x & 31;
    if (gw >= N_) return;
    int off = lane * 2;
    float2 xr2 = *(const float2*)&g_xr[gw * 64 + off];
    float2 a2  = *(const float2*)&att[off];
    float2 xls = ldxl64(gw, off);

    float m = edot2(xls, xr2, a2), s = 1.f;
    float2 acc = xls;

    int beg = g_rowptr[gw], end = g_rowptr[gw + 1];
    int j = beg;
    for (; j + 3 < end; j += 4) {
        int s0 = g_col[j], s1 = g_col[j + 1], s2 = g_col[j + 2], s3 = g_col[j + 3];
        float2 v0 = ldxl64(s0, off);
        float2 v1 = ldxl64(s1, off);
        float2 v2 = ldxl64(s2, off);
        float2 v3 = ldxl64(s3, off);
        float q0 = edot2(v0, xr2, a2);
        float q1 = edot2(v1, xr2, a2);
        float q2 = edot2(v2, xr2, a2);
        float q3 = edot2(v3, xr2, a2);
        float nm = fmaxf(fmaxf(m, fmaxf(q0, q1)), fmaxf(q2, q3));
        float co = __expf(m - nm);
        float w0 = __expf(q0 - nm);
        float w1 = __expf(q1 - nm);
        float w2 = __expf(q2 - nm);
        float w3 = __expf(q3 - nm);
        s = s * co + w0 + w1 + w2 + w3;
        acc.x = acc.x * co + w0 * v0.x + w1 * v1.x + w2 * v2.x + w3 * v3.x;
        acc.y = acc.y * co + w0 * v0.y + w1 * v1.y + w2 * v2.y + w3 * v3.y;
        m = nm;
    }
    for (; j < end; j++) {
        int src = g_col[j];
        float2 v = ldxl64(src, off);
        float q = edot2(v, xr2, a2);
        float nm = fmaxf(m, q);
        float co = __expf(m - nm);
        float w  = __expf(q - nm);
        s = s * co + w;
        acc.x = acc.x * co + w * v.x;
        acc.y = acc.y * co + w * v.y;
        m = nm;
    }
    float inv = 1.f / s;
    float o0 = acc.x * inv + bias[off];
    float o1 = acc.y * inv + bias[off + 1];

    float mx = fmaxf(o0, o1);
#pragma unroll
    for (int d = 16; d >= 1; d >>= 1)
        mx = fmaxf(mx, __shfl_xor_sync(0xffffffffu, mx, d));
    float se = __expf(o0 - mx) + __expf(o1 - mx);
#pragma unroll
    for (int d = 16; d >= 1; d >>= 1)
        se += __shfl_xor_sync(0xffffffffu, se, d);
    float lse = logf(se);
    outp[gw * 64 + off]     = o0 - mx - lse;
    outp[gw * 64 + off + 1] = o1 - mx - lse;
}

// ---------------------------------------------------------------------------
// Host launch — R6 schedule: CSR on side stream hidden under gemm1,
// then serial layer chain.
// ---------------------------------------------------------------------------
extern "C" void kernel_launch(void* const* d_in, const int* in_sizes, int n_in,
                              void* d_out, int out_size) {
    const float* x    = (const float*)d_in[0];
    const void*  ei   = d_in[1];
    const float* Wl1  = (const float*)d_in[2];
    const float* Wr1  = (const float*)d_in[3];
    const float* att1 = (const float*)d_in[4];
    const float* b1   = (const float*)d_in[5];
    const float* Wl2  = (const float*)d_in[6];
    const float* Wr2  = (const float*)d_in[7];
    const float* att2 = (const float*)d_in[8];
    const float* b2   = (const float*)d_in[9];
    const float* Wl3  = (const float*)d_in[10];
    const float* Wr3  = (const float*)d_in[11];
    const float* att3 = (const float*)d_in[12];
    const float* b3   = (const float*)d_in[13];
    float* out = (float*)d_out;

    static cudaStream_t s2 = nullptr;
    static cudaEvent_t evFork = nullptr, evJoin = nullptr;
    if (s2 == nullptr) {
        cudaStreamCreateWithFlags(&s2, cudaStreamNonBlocking);
        cudaEventCreateWithFlags(&evFork, cudaEventDisableTiming);
        cudaEventCreateWithFlags(&evJoin, cudaEventDisableTiming);
    }

    dim3 g12((N_ + 127) / 128, 4);
    dim3 g3 ((N_ + 127) / 128, 2);
    int aggBlocks = (N_ * 32 + 255) / 256;

    // Fork: CSR build on s2, concurrent with layer-1 GEMM on main stream
    cudaEventRecord(evFork, 0);
    cudaStreamWaitEvent(s2, evFork, 0);

    k_detect_zero<<<(N_ + 255) / 256, 256, 0, s2>>>((const int*)ei);
    k_convert_hist<<<(E_ + 255) / 256, 256, 0, s2>>>(ei);
    k_scan1<<<NB_SCAN, 1024, 0, s2>>>();
    k_scan2<<<1, 64, 0, s2>>>();
    k_scan3<<<(N_ + 255) / 256, 256, 0, s2>>>();
    k_scatter<<<(E_ + 255) / 256, 256, 0, s2>>>();
    cudaEventRecord(evJoin, s2);

    // Layer-1 GEMM on main stream (independent of CSR)
    k_gemm_fp16<128, 0><<<g12, 256>>>(x, Wl1, Wr1);
    cudaStreamWaitEvent(0, evJoin, 0);

    k_agg128<<<aggBlocks, 256>>>(att1, b1);
    // Layer 2
    k_gemm_fp16<128, 1><<<g12, 256>>>(nullptr, Wl2, Wr2);
    k_agg128<<<aggBlocks, 256>>>(att2, b2);
    // Layer 3 + log_softmax
    k_gemm_fp16<64, 1><<<g3, 256>>>(nullptr, Wl3, Wr3);
    k_agg64<<<aggBlocks, 256>>>(att3, b3, out);
}

// round 17
// speedup vs baseline: 1.0119x; 1.0042x over previous
#include <cuda_runtime.h>
#include <cuda_fp16.h>
#include <math.h>
#include <stdint.h>

// Problem constants (fixed by the dataset)
#define N_ 50000
#define E_ 800000
#define NB_SCAN ((N_ + 1023) / 1024)   // 49

// ---------------------------------------------------------------------------
// Static device scratch. xl fp16 (gathered per edge), xr/h fp32.
// ---------------------------------------------------------------------------
__device__ __align__(16) __half g_xlh[N_ * 128];
__device__ __align__(16) float  g_xr [N_ * 128];
__device__ __align__(16) float  g_h  [N_ * 128];
__device__ int   g_rowptr[N_ + 1];
__device__ int   g_cnt[N_];
__device__ int   g_col[E_];
__device__ int   g_esrc[E_];
__device__ int   g_edst[E_];
__device__ int   g_is64;
__device__ int   g_bsum[64];
__device__ int   g_boff[64];

// ---------------------------------------------------------------------------
// Edge-index dtype sniff + zero counters (fused)
// ---------------------------------------------------------------------------
__global__ void k_detect_zero(const int* __restrict__ ei32) {
    int i = blockIdx.x * blockDim.x + threadIdx.x;
    if (i < N_) g_cnt[i] = 0;
    if (blockIdx.x == 0) {
        __shared__ int nz;
        if (threadIdx.x == 0) nz = 0;
        __syncthreads();
        int local = 0;
        for (int k = threadIdx.x; k < 4096; k += blockDim.x)
            local |= ei32[2 * k + 1];
        if (local) atomicOr(&nz, 1);
        __syncthreads();
        if (threadIdx.x == 0) g_is64 = (nz == 0) ? 1 : 0;
    }
}

__global__ void k_convert_hist(const void* __restrict__ ei) {
    int e = blockIdx.x * blockDim.x + threadIdx.x;
    if (e >= E_) return;
    int s, d;
    if (g_is64) {
        const long long* p = (const long long*)ei;
        s = (int)p[e];
        d = (int)p[E_ + e];
    } else {
        const int* p = (const int*)ei;
        s = p[e];
        d = p[E_ + e];
    }
    s = min(max(s, 0), N_ - 1);
    d = min(max(d, 0), N_ - 1);
    g_esrc[e] = s;
    g_edst[e] = d;
    atomicAdd(&g_cnt[d], 1);
}

// ---------------------------------------------------------------------------
// Multi-block exclusive scan of g_cnt -> g_rowptr (3 phases)
// ---------------------------------------------------------------------------
__global__ void k_scan1() {
    __shared__ int sh[1024];
    int b = blockIdx.x, t = threadIdx.x;
    int idx = b * 1024 + t;
    int v = (idx < N_) ? g_cnt[idx] : 0;
    sh[t] = v;
    __syncthreads();
#pragma unroll
    for (int off = 1; off < 1024; off <<= 1) {
        int x = (t >= off) ? sh[t - off] : 0;
        __syncthreads();
        sh[t] += x;
        __syncthreads();
    }
    if (idx < N_) g_rowptr[idx] = sh[t] - v;
    if (t == 1023) g_bsum[b] = sh[1023];
}

__global__ void k_scan2() {
    __shared__ int sh[64];
    int t = threadIdx.x;
    int v = (t < NB_SCAN) ? g_bsum[t] : 0;
    sh[t] = v;
    __syncthreads();
#pragma unroll
    for (int off = 1; off < 64; off <<= 1) {
        int x = (t >= off) ? sh[t - off] : 0;
        __syncthreads();
        sh[t] += x;
        __syncthreads();
    }
    if (t < NB_SCAN) g_boff[t] = sh[t] - v;
    if (t == 63) g_rowptr[N_] = sh[63];
}

__global__ void k_scan3() {
    int i = blockIdx.x * blockDim.x + threadIdx.x;
    if (i < N_) {
        g_rowptr[i] += g_boff[i >> 10];
        g_cnt[i] = 0;
    }
}

__global__ void k_scatter() {
    int e = blockIdx.x * blockDim.x + threadIdx.x;
    if (e < E_) {
        int d = g_edst[e];
        int p = atomicAdd(&g_cnt[d], 1);
        int pos = g_rowptr[d] + p;
        if (pos >= 0 && pos < E_) g_col[pos] = g_esrc[e];
    }
}

// ---------------------------------------------------------------------------
// fp16 tensor-core fused dual GEMM (m16n8k16.f16, fp32 accum):
//   xl (fp16) = A @ Wl, xr (fp32) = A @ Wr   (A: [N,128], W: [128,HALF])
// Block tile 128x64, 8 warps (4Mx2N), warp tile 32x32, K chunks of 32,
// double-buffered packed-half2 smem. fp16 mantissa == tf32 mantissa (10 bits),
// so numerics match the previous tf32 version while halving HMMA count.
// ---------------------------------------------------------------------------
__device__ __forceinline__ void mma_f16(float c[4], const uint32_t a[4], const uint32_t b[2]) {
    asm volatile(
        "mma.sync.aligned.m16n8k16.row.col.f32.f16.f16.f32 "
        "{%0,%1,%2,%3}, {%4,%5,%6,%7}, {%8,%9}, {%0,%1,%2,%3};"
        : "+f"(c[0]), "+f"(c[1]), "+f"(c[2]), "+f"(c[3])
        : "r"(a[0]), "r"(a[1]), "r"(a[2]), "r"(a[3]), "r"(b[0]), "r"(b[1]));
}

__device__ __forceinline__ uint32_t pack_h2(float x, float y) {
    __half2 h = __floats2half2_rn(x, y);
    return *reinterpret_cast<uint32_t*>(&h);
}

template <int HALF, int AFROMH>
__global__ void __launch_bounds__(256) k_gemm_fp16(const float* __restrict__ A_ext,
                                                   const float* __restrict__ Wl,
                                                   const float* __restrict__ Wr) {
    // packed half2 tiles: column j holds k = 2j, 2j+1. Row stride 20 (pad 4)
    // -> fragment LDS banks (20*g + tig) % 32 all-distinct: conflict-free.
    __shared__ uint32_t As16[2][128][20];   // [row][j], j in [0,16)
    __shared__ uint32_t Bs16[2][64][20];    // [n]  [j], j in [0,16)

    const float* A = AFROMH ? (const float*)g_h : A_ext;

    const int HT = HALF / 64;
    int row0 = blockIdx.x * 128;
    int by = blockIdx.y;
    bool isXL = (by < HT);
    const float* W = isXL ? Wl : Wr;
    int colbase = (by % HT) * 64;

    int tid  = threadIdx.x;
    int lane = tid & 31;
    int wid  = tid >> 5;
    int warpM = wid & 3;
    int warpN = wid >> 2;
    int g   = lane >> 2;
    int tig = lane & 3;
    int mrow = warpM * 32;
    int ncol = warpN * 32;

    // staging coords: A: 1024 float4 (128 rows x 8), B: 1024 uint32 (16j x 64n)
    int ra_r[4], ra_kq[4], rb_j[4], rb_n[4];
#pragma unroll
    for (int l = 0; l < 4; l++) {
        int idx = tid + l * 256;
        ra_r[l]  = idx >> 3;
        ra_kq[l] = idx & 7;
        rb_j[l]  = idx >> 6;
        rb_n[l]  = idx & 63;
    }

    float c[2][4][4];
#pragma unroll
    for (int mt = 0; mt < 2; mt++)
#pragma unroll
        for (int nt = 0; nt < 4; nt++)
#pragma unroll
            for (int i = 0; i < 4; i++) c[mt][nt][i] = 0.f;

    // Prologue: chunk 0 -> buffer 0
    {
#pragma unroll
        for (int l = 0; l < 4; l++) {
            int grow = row0 + ra_r[l];
            float4 v = make_float4(0.f, 0.f, 0.f, 0.f);
            if (grow < N_) v = *(const float4*)&A[grow * 128 + ra_kq[l] * 4];
            As16[0][ra_r[l]][ra_kq[l] * 2    ] = pack_h2(v.x, v.y);
            As16[0][ra_r[l]][ra_kq[l] * 2 + 1] = pack_h2(v.z, v.w);
        }
#pragma unroll
        for (int l = 0; l < 4; l++) {
            float w0 = W[(2 * rb_j[l]    ) * HALF + colbase + rb_n[l]];
            float w1 = W[(2 * rb_j[l] + 1) * HALF + colbase + rb_n[l]];
            Bs16[0][rb_n[l]][rb_j[l]] = pack_h2(w0, w1);
        }
    }
    __syncthreads();

    for (int kc = 0; kc < 4; kc++) {
        int cur = kc & 1;
        // prefetch next chunk into registers
        float4 pa[4];
        float pb0[4], pb1[4];
        if (kc < 3) {
            int kn = kc + 1;
#pragma unroll
            for (int l = 0; l < 4; l++) {
                int grow = row0 + ra_r[l];
                pa[l] = make_float4(0.f, 0.f, 0.f, 0.f);
                if (grow < N_) pa[l] = *(const float4*)&A[grow * 128 + kn * 32 + ra_kq[l] * 4];
            }
#pragma unroll
            for (int l = 0; l < 4; l++) {
                pb0[l] = W[(kn * 32 + 2 * rb_j[l]    ) * HALF + colbase + rb_n[l]];
                pb1[l] = W[(kn * 32 + 2 * rb_j[l] + 1) * HALF + colbase + rb_n[l]];
            }
        }

#pragma unroll
        for (int ks = 0; ks < 2; ks++) {
            int j0 = ks * 8;
            uint32_t a[2][4], b[4][2];
#pragma unroll
            for (int mt = 0; mt < 2; mt++) {
                int r = mrow + mt * 16 + g;
                a[mt][0] = As16[cur][r    ][j0 + tig];
                a[mt][1] = As16[cur][r + 8][j0 + tig];
                a[mt][2] = As16[cur][r    ][j0 + tig + 4];
                a[mt][3] = As16[cur][r + 8][j0 + tig + 4];
            }
#pragma unroll
            for (int nt = 0; nt < 4; nt++) {
                int n = ncol + nt * 8 + g;
                b[nt][0] = Bs16[cur][n][j0 + tig];
                b[nt][1] = Bs16[cur][n][j0 + tig + 4];
            }
#pragma unroll
            for (int mt = 0; mt < 2; mt++)
#pragma unroll
                for (int nt = 0; nt < 4; nt++)
                    mma_f16(c[mt][nt], a[mt], b[nt]);
        }

        if (kc < 3) {
            int nxt = cur ^ 1;
#pragma unroll
            for (int l = 0; l < 4; l++) {
                As16[nxt][ra_r[l]][ra_kq[l] * 2    ] = pack_h2(pa[l].x, pa[l].y);
                As16[nxt][ra_r[l]][ra_kq[l] * 2 + 1] = pack_h2(pa[l].z, pa[l].w);
            }
#pragma unroll
            for (int l = 0; l < 4; l++)
                Bs16[nxt][rb_n[l]][rb_j[l]] = pack_h2(pb0[l], pb1[l]);
        }
        __syncthreads();
    }

    // Epilogue: xl -> fp16, xr -> fp32
#pragma unroll
    for (int mt = 0; mt < 2; mt++) {
        int r0 = row0 + mrow + mt * 16 + g;
#pragma unroll
        for (int nt = 0; nt < 4; nt++) {
            int cb = colbase + ncol + nt * 8 + tig * 2;
            if (isXL) {
                if (r0 < N_)
                    *(__half2*)&g_xlh[r0 * HALF + cb] =
                        __floats2half2_rn(c[mt][nt][0], c[mt][nt][1]);
                if (r0 + 8 < N_)
                    *(__half2*)&g_xlh[(r0 + 8) * HALF + cb] =
                        __floats2half2_rn(c[mt][nt][2], c[mt][nt][3]);
            } else {
                if (r0 < N_)
                    *(float2*)&g_xr[r0 * HALF + cb] = make_float2(c[mt][nt][0], c[mt][nt][1]);
                if (r0 + 8 < N_)
                    *(float2*)&g_xr[(r0 + 8) * HALF + cb] = make_float2(c[mt][nt][2], c[mt][nt][3]);
            }
        }
    }
}

// ---------------------------------------------------------------------------
// fp16 gather helpers
// ---------------------------------------------------------------------------
__device__ __forceinline__ float4 ldxl128(int node, int off) {
    uint2 u = *(const uint2*)&g_xlh[node * 128 + off];
    __half2 h0 = *reinterpret_cast<__half2*>(&u.x);
    __half2 h1 = *reinterpret_cast<__half2*>(&u.y);
    float2 a = __half22float2(h0);
    float2 b = __half22float2(h1);
    return make_float4(a.x, a.y, b.x, b.y);
}

__device__ __forceinline__ float2 ldxl64(int node, int off) {
    __half2 h = *(const __half2*)&g_xlh[node * 64 + off];
    return __half22float2(h);
}

// ---------------------------------------------------------------------------
// Edge aggregation: one warp per dst node, online segment softmax, 4-edge
// unrolled, fused bias + ELU (layers 1/2, 128 channels)
// ---------------------------------------------------------------------------
__device__ __forceinline__ float leaky(float x) { return x > 0.f ? x : 0.2f * x; }

__device__ __forceinline__ float edot(const float4 v, const float4 xr, const float4 a) {
    float q = leaky(v.x + xr.x) * a.x + leaky(v.y + xr.y) * a.y
            + leaky(v.z + xr.z) * a.z + leaky(v.w + xr.w) * a.w;
    q += __shfl_xor_sync(0xffffffffu, q, 1);
    q += __shfl_xor_sync(0xffffffffu, q, 2);
    q += __shfl_xor_sync(0xffffffffu, q, 4);
    return q;
}

__global__ void k_agg128(const float* __restrict__ att,
                         const float* __restrict__ bias) {
    int gw = (blockIdx.x * blockDim.x + threadIdx.x) >> 5;
    int lane = threadIdx.x & 31;
    if (gw >= N_) return;
    int off = lane * 4;
    float4 xr4 = *(const float4*)&g_xr[gw * 128 + off];
    float4 a4  = *(const float4*)&att[off];
    float4 xls = ldxl128(gw, off);

    float m = edot(xls, xr4, a4), s = 1.f;
    float4 acc = xls;

    int beg = g_rowptr[gw], end = g_rowptr[gw + 1];
    int j = beg;
    for (; j + 3 < end; j += 4) {
        int s0 = g_col[j], s1 = g_col[j + 1], s2 = g_col[j + 2], s3 = g_col[j + 3];
        float4 v0 = ldxl128(s0, off);
        float4 v1 = ldxl128(s1, off);
        float4 v2 = ldxl128(s2, off);
        float4 v3 = ldxl128(s3, off);
        float q0 = edot(v0, xr4, a4);
        float q1 = edot(v1, xr4, a4);
        float q2 = edot(v2, xr4, a4);
        float q3 = edot(v3, xr4, a4);
        float nm = fmaxf(fmaxf(m, fmaxf(q0, q1)), fmaxf(q2, q3));
        float co = __expf(m - nm);
        float w0 = __expf(q0 - nm);
        float w1 = __expf(q1 - nm);
        float w2 = __expf(q2 - nm);
        float w3 = __expf(q3 - nm);
        s = s * co + w0 + w1 + w2 + w3;
        acc.x = acc.x * co + w0 * v0.x + w1 * v1.x + w2 * v2.x + w3 * v3.x;
        acc.y = acc.y * co + w0 * v0.y + w1 * v1.y + w2 * v2.y + w3 * v3.y;
        acc.z = acc.z * co + w0 * v0.z + w1 * v1.z + w2 * v2.z + w3 * v3.z;
        acc.w = acc.w * co + w0 * v0.w + w1 * v1.w + w2 * v2.w + w3 * v3.w;
        m = nm;
    }
    for (; j < end; j++) {
        int src = g_col[j];
        float4 v = ldxl128(src, off);
        float q = edot(v, xr4, a4);
        float nm = fmaxf(m, q);
        float co = __expf(m - nm);
        float w  = __expf(q - nm);
        s = s * co + w;
        acc.x = acc.x * co + w * v.x;
        acc.y = acc.y * co + w * v.y;
        acc.z = acc.z * co + w * v.z;
        acc.w = acc.w * co + w * v.w;
        m = nm;
    }
    float inv = 1.f / s;
    float4 b4 = *(const float4*)&bias[off];
    float4 o;
    o.x = acc.x * inv + b4.x;
    o.y = acc.y * inv + b4.y;
    o.z = acc.z * inv + b4.z;
    o.w = acc.w * inv + b4.w;
    o.x = o.x > 0.f ? o.x : expm1f(o.x);
    o.y = o.y > 0.f ? o.y : expm1f(o.y);
    o.z = o.z > 0.f ? o.z : expm1f(o.z);
    o.w = o.w > 0.f ? o.w : expm1f(o.w);
    *(float4*)&g_h[gw * 128 + off] = o;
}

// ---------------------------------------------------------------------------
// Layer-3 aggregation (64 channels; lane owns 2), fused bias + log_softmax
// ---------------------------------------------------------------------------
__device__ __forceinline__ float edot2(const float2 v, const float2 xr, const float2 a) {
    float q = leaky(v.x + xr.x) * a.x + leaky(v.y + xr.y) * a.y;
    q += __shfl_xor_sync(0xffffffffu, q, 1);
    q += __shfl_xor_sync(0xffffffffu, q, 2);
    q += __shfl_xor_sync(0xffffffffu, q, 4);
    return q;
}

__global__ void k_agg64(const float* __restrict__ att,
                        const float* __restrict__ bias,
                        float* __restrict__ outp) {
    int gw = (blockIdx.x * blockDim.x + threadIdx.x) >> 5;
    int lane = threadIdx.x & 31;
    if (gw >= N_) return;
    int off = lane * 2;
    float2 xr2 = *(const float2*)&g_xr[gw * 64 + off];
    float2 a2  = *(const float2*)&att[off];
    float2 xls = ldxl64(gw, off);

    float m = edot2(xls, xr2, a2), s = 1.f;
    float2 acc = xls;

    int beg = g_rowptr[gw], end = g_rowptr[gw + 1];
    int j = beg;
    for (; j + 3 < end; j += 4) {
        int s0 = g_col[j], s1 = g_col[j + 1], s2 = g_col[j + 2], s3 = g_col[j + 3];
        float2 v0 = ldxl64(s0, off);
        float2 v1 = ldxl64(s1, off);
        float2 v2 = ldxl64(s2, off);
        float2 v3 = ldxl64(s3, off);
        float q0 = edot2(v0, xr2, a2);
        float q1 = edot2(v1, xr2, a2);
        float q2 = edot2(v2, xr2, a2);
        float q3 = edot2(v3, xr2, a2);
        float nm = fmaxf(fmaxf(m, fmaxf(q0, q1)), fmaxf(q2, q3));
        float co = __expf(m - nm);
        float w0 = __expf(q0 - nm);
        float w1 = __expf(q1 - nm);
        float w2 = __expf(q2 - nm);
        float w3 = __expf(q3 - nm);
        s = s * co + w0 + w1 + w2 + w3;
        acc.x = acc.x * co + w0 * v0.x + w1 * v1.x + w2 * v2.x + w3 * v3.x;
        acc.y = acc.y * co + w0 * v0.y + w1 * v1.y + w2 * v2.y + w3 * v3.y;
        m = nm;
    }
    for (; j < end; j++) {
        int src = g_col[j];
        float2 v = ldxl64(src, off);
        float q = edot2(v, xr2, a2);
        float nm = fmaxf(m, q);
        float co = __expf(m - nm);
        float w  = __expf(q - nm);
        s = s * co + w;
        acc.x = acc.x * co + w * v.x;
        acc.y = acc.y * co + w * v.y;
        m = nm;
    }
    float inv = 1.f / s;
    float o0 = acc.x * inv + bias[off];
    float o1 = acc.y * inv + bias[off + 1];

    float mx = fmaxf(o0, o1);
#pragma unroll
    for (int d = 16; d >= 1; d >>= 1)
        mx = fmaxf(mx, __shfl_xor_sync(0xffffffffu, mx, d));
    float se = __expf(o0 - mx) + __expf(o1 - mx);
#pragma unroll
    for (int d = 16; d >= 1; d >>= 1)
        se += __shfl_xor_sync(0xffffffffu, se, d);
    float lse = logf(se);
    outp[gw * 64 + off]     = o0 - mx - lse;
    outp[gw * 64 + off + 1] = o1 - mx - lse;
}

// ---------------------------------------------------------------------------
// Host launch — R6 schedule: CSR on side stream hidden under gemm1,
// then serial layer chain.
// ---------------------------------------------------------------------------
extern "C" void kernel_launch(void* const* d_in, const int* in_sizes, int n_in,
                              void* d_out, int out_size) {
    const float* x    = (const float*)d_in[0];
    const void*  ei   = d_in[1];
    const float* Wl1  = (const float*)d_in[2];
    const float* Wr1  = (const float*)d_in[3];
    const float* att1 = (const float*)d_in[4];
    const float* b1   = (const float*)d_in[5];
    const float* Wl2  = (const float*)d_in[6];
    const float* Wr2  = (const float*)d_in[7];
    const float* att2 = (const float*)d_in[8];
    const float* b2   = (const float*)d_in[9];
    const float* Wl3  = (const float*)d_in[10];
    const float* Wr3  = (const float*)d_in[11];
    const float* att3 = (const float*)d_in[12];
    const float* b3   = (const float*)d_in[13];
    float* out = (float*)d_out;

    static cudaStream_t s2 = nullptr;
    static cudaEvent_t evFork = nullptr, evJoin = nullptr;
    if (s2 == nullptr) {
        cudaStreamCreateWithFlags(&s2, cudaStreamNonBlocking);
        cudaEventCreateWithFlags(&evFork, cudaEventDisableTiming);
        cudaEventCreateWithFlags(&evJoin, cudaEventDisableTiming);
    }

    dim3 g12((N_ + 127) / 128, 4);
    dim3 g3 ((N_ + 127) / 128, 2);
    int aggBlocks = (N_ * 32 + 255) / 256;

    // Fork: CSR build on s2, concurrent with layer-1 GEMM on main stream
    cudaEventRecord(evFork, 0);
    cudaStreamWaitEvent(s2, evFork, 0);

    k_detect_zero<<<(N_ + 255) / 256, 256, 0, s2>>>((const int*)ei);
    k_convert_hist<<<(E_ + 255) / 256, 256, 0, s2>>>(ei);
    k_scan1<<<NB_SCAN, 1024, 0, s2>>>();
    k_scan2<<<1, 64, 0, s2>>>();
    k_scan3<<<(N_ + 255) / 256, 256, 0, s2>>>();
    k_scatter<<<(E_ + 255) / 256, 256, 0, s2>>>();
    cudaEventRecord(evJoin, s2);

    // Layer-1 GEMM on main stream (independent of CSR)
    k_gemm_fp16<128, 0><<<g12, 256>>>(x, Wl1, Wr1);
    cudaStreamWaitEvent(0, evJoin, 0);

    k_agg128<<<aggBlocks, 256>>>(att1, b1);
    // Layer 2
    k_gemm_fp16<128, 1><<<g12, 256>>>(nullptr, Wl2, Wr2);
    k_agg128<<<aggBlocks, 256>>>(att2, b2);
    // Layer 3 + log_softmax
    k_gemm_fp16<64, 1><<<g3, 256>>>(nullptr, Wl3, Wr3);
    k_agg64<<<aggBlocks, 256>>>(att3, b3, out);
}